// round 15
// baseline (speedup 1.0000x reference)
#include <cuda_runtime.h>
#include <cstdint>
#include <math.h>
#include <cuda_fp16.h>
#include <mma.h>
using namespace nvcuda;

// Fixed problem shapes
#define BB   4
#define SS   4096
#define DDIM 512
#define HH   2048
#define LL   3
#define MMR  (BB*SS)      // 16384 rows
#define CHK  128          // scan chunk length (per-thread serial)
#define NCH  (SS/CHK)     // 32 chunks per sequence

// GEMM tiling: 128x128 CTA tile, 8 warps (64x32), KTILE=32, 5-stage pipeline
#define KTILE 32
#define LDSA  40               // smem stride in halfs (32 + 8 pad; 80B = 5x16B)
#define ATILE (128*LDSA)       // 5120 halfs = 10240 B
#define STAGE (2*ATILE)        // A+B per stage (halfs)
#define NSTG  5
#define SMEMSZ (NSTG*STAGE*2)  // 102400 bytes (epilogue aliases stage 0)
#define NTHR  256

// ---------------- scratch (static device arrays; no allocation) --------------
__device__ float  g_xbuf[MMR*DDIM];   // residual stream (fp32)
__device__ float  g_P [BB*DDIM*NCH];
__device__ float  g_V [BB*DDIM*NCH];
__device__ float  g_Hi[BB*DDIM*NCH];
__device__ __half g_c16 [MMR*DDIM];   // gate c (fp16)
__device__ __half g_v16 [MMR*DDIM];   // gate v (fp16)
__device__ __half g_gin16[MMR*DDIM];  // LN outputs (GEMM A operand)
__device__ __half g_cin16[MMR*DDIM];  // dwconv out / mlp_in (GEMM A operand)
__device__ __half g_h16 [MMR*HH];     // MLP hidden (fp16)
// fp16 transposed weights [N][K]
__device__ __half g_Wzh16[LL*2*DDIM*DDIM];  // interleaved [1024][512] per layer
__device__ __half g_W1T16[HH*DDIM];
__device__ __half g_W2T16[DDIM*HH];
__device__ __half g_pw16 [DDIM*DDIM];

// ---------------- fp16 tensor-core GEMM, 128x128x32, 8 warps, 5-stage --------
// C[m,n] = sum_k A[m,k] * Bt[n,k]   (A fp16 [M,K], Bt fp16 [N,K], fp32 accum)
__device__ __forceinline__ void cpasync16(void* dst, const void* src)
{
    unsigned int d = (unsigned int)__cvta_generic_to_shared(dst);
    asm volatile("cp.async.cg.shared.global [%0], [%1], 16;\n" :: "r"(d), "l"(src));
}

__global__ void __launch_bounds__(NTHR, 2)
hgemm_kernel(const __half* __restrict__ A, const __half* __restrict__ Bt,
             float* __restrict__ C, __half* __restrict__ C16,
             __half* __restrict__ gateC, __half* __restrict__ gateV,
             int M, int N, int K,
             const float* __restrict__ bias, const float* __restrict__ resid,
             int dorelu)
{
    extern __shared__ __half smh[];
    float* epist = (float*)smh;       // aliases stage 0 (used post-mainloop)

    const int tid = threadIdx.x;
    const int wid = tid >> 5;
    const int lane = tid & 31;
    const int bm = blockIdx.y * 128;
    const int bn = blockIdx.x * 128;
    const int wm = (wid >> 2) * 64;   // warp grid 2(m) x 4(n)
    const int wn = (wid & 3) * 32;
    float* wbuf = epist + wid*256;    // per-warp 16x16 staging

    wmma::fragment<wmma::accumulator, 16, 16, 16, float> acc[4][2];
    #pragma unroll
    for (int i = 0; i < 4; i++)
        #pragma unroll
        for (int j = 0; j < 2; j++) wmma::fill_fragment(acc[i][j], 0.f);

    // ---- stage loaders: 128 rows x 32 halfs = 512 16B-chunks -> 2/thread ----
    auto loadStage = [&](int stg, int k0) {
        __half* As = smh + stg*STAGE;
        __half* Bs = As + ATILE;
        #pragma unroll
        for (int i = 0; i < 2; i++) {
            int idx = tid + i*NTHR;
            int r = idx >> 2, c8 = (idx & 3) * 8;
            cpasync16(As + r*LDSA + c8, A + (size_t)(bm + r)*K + k0 + c8);
        }
        #pragma unroll
        for (int i = 0; i < 2; i++) {
            int idx = tid + i*NTHR;
            int r = idx >> 2, c8 = (idx & 3) * 8;
            cpasync16(Bs + r*LDSA + c8, Bt + (size_t)(bn + r)*K + k0 + c8);
        }
        asm volatile("cp.async.commit_group;\n");
    };

    const int nk = K / KTILE;
    #pragma unroll
    for (int s = 0; s < 4; s++)
        if (s < nk) loadStage(s, s*KTILE);

    for (int kt = 0; kt < nk; kt++) {
        int rem = nk - kt - 1;            // groups allowed to stay pending
        if (rem >= 3)      asm volatile("cp.async.wait_group 3;\n");
        else if (rem == 2) asm volatile("cp.async.wait_group 2;\n");
        else if (rem == 1) asm volatile("cp.async.wait_group 1;\n");
        else               asm volatile("cp.async.wait_group 0;\n");
        __syncthreads();
        if (kt + 4 < nk) loadStage((kt+4) % NSTG, (kt+4)*KTILE);

        const __half* a = smh + (kt % NSTG)*STAGE;
        const __half* b = a + ATILE;
        #pragma unroll
        for (int ks = 0; ks < 2; ks++) {
            const int kk = ks * 16;
            wmma::fragment<wmma::matrix_a, 16, 16, 16, half, wmma::row_major> af[4];
            #pragma unroll
            for (int i = 0; i < 4; i++)
                wmma::load_matrix_sync(af[i], a + (wm + i*16)*LDSA + kk, LDSA);
            wmma::fragment<wmma::matrix_b, 16, 16, 16, half, wmma::col_major> bf[2];
            #pragma unroll
            for (int j = 0; j < 2; j++)
                wmma::load_matrix_sync(bf[j], b + (wn + j*16)*LDSA + kk, LDSA);
            #pragma unroll
            for (int i = 0; i < 4; i++)
                #pragma unroll
                for (int j = 0; j < 2; j++)
                    wmma::mma_sync(acc[i][j], af[i], bf[j], acc[i][j]);
        }
    }
    __syncthreads();   // protect epilogue staging (aliases stage 0)

    // ---- epilogue: per-warp 16x16 staging ----
    #pragma unroll
    for (int i = 0; i < 4; i++) {
        #pragma unroll
        for (int j = 0; j < 2; j++) {
            wmma::store_matrix_sync(wbuf, acc[i][j], 16, wmma::mem_row_major);
            __syncwarp();
            int r = lane >> 1, c = (lane & 1) * 8;
            int row = bm + wm + i*16 + r;
            int col = bn + wn + j*16 + c;
            float4 v0 = *(float4*)&wbuf[r*16 + c];
            float4 v1 = *(float4*)&wbuf[r*16 + c + 4];
            if (gateC) {
                // interleaved cols: (k0,a0,k1,a1,...) -> 4 (k,a) pairs
                float kk_[4] = { v0.x, v0.z, v1.x, v1.z };
                float aa_[4] = { v0.y, v0.w, v1.y, v1.w };
                __half cw[4], vw[4];
                #pragma unroll
                for (int t = 0; t < 4; t++) {
                    float e  = __expf(kk_[t]);
                    float ci = 1.f / (1.f + e);      // sigmoid(-k)
                    float zi = e * ci;               // sigmoid(k)
                    float a  = aa_[t];
                    float gg = (a >= 0.f) ? (a + 0.5f)
                                          : (1.f / (1.f + __expf(-a)));
                    cw[t] = __float2half(ci);
                    vw[t] = __float2half(zi * gg);
                }
                int p = col >> 1;    // pair index 0..511
                *(uint2*)&gateC[(size_t)row*DDIM + p] = *(uint2*)cw;
                *(uint2*)&gateV[(size_t)row*DDIM + p] = *(uint2*)vw;
            } else {
                if (bias) {
                    float4 b0 = *(const float4*)&bias[col];
                    float4 b1 = *(const float4*)&bias[col+4];
                    v0.x += b0.x; v0.y += b0.y; v0.z += b0.z; v0.w += b0.w;
                    v1.x += b1.x; v1.y += b1.y; v1.z += b1.z; v1.w += b1.w;
                }
                if (dorelu) {
                    v0.x = fmaxf(v0.x, 0.f); v0.y = fmaxf(v0.y, 0.f);
                    v0.z = fmaxf(v0.z, 0.f); v0.w = fmaxf(v0.w, 0.f);
                    v1.x = fmaxf(v1.x, 0.f); v1.y = fmaxf(v1.y, 0.f);
                    v1.z = fmaxf(v1.z, 0.f); v1.w = fmaxf(v1.w, 0.f);
                }
                if (resid) {
                    float4 r0 = *(const float4*)&resid[(size_t)row*N + col];
                    float4 r1 = *(const float4*)&resid[(size_t)row*N + col + 4];
                    v0.x += r0.x; v0.y += r0.y; v0.z += r0.z; v0.w += r0.w;
                    v1.x += r1.x; v1.y += r1.y; v1.z += r1.z; v1.w += r1.w;
                }
                if (C16) {
                    __half2 h[4];
                    h[0] = __floats2half2_rn(v0.x, v0.y);
                    h[1] = __floats2half2_rn(v0.z, v0.w);
                    h[2] = __floats2half2_rn(v1.x, v1.y);
                    h[3] = __floats2half2_rn(v1.z, v1.w);
                    *(uint4*)&C16[(size_t)row*N + col] = *(uint4*)h;
                } else {
                    *(float4*)&C[(size_t)row*N + col]     = v0;
                    *(float4*)&C[(size_t)row*N + col + 4] = v1;
                }
            }
            __syncwarp();
        }
    }
}

// ---------------- weight transpose+convert: out16[n*K+k] = in[k*N+n] ---------
__global__ void transpose_h(const float* __restrict__ in, __half* __restrict__ out,
                            int K, int N)
{
    __shared__ float t[32][33];
    int z = blockIdx.z;
    in  += (size_t)z * K * N;
    out += (size_t)z * K * N;
    int n0 = blockIdx.x * 32, k0 = blockIdx.y * 32;
    #pragma unroll
    for (int i = 0; i < 4; i++)
        t[threadIdx.y + i*8][threadIdx.x] =
            in[(size_t)(k0 + threadIdx.y + i*8) * N + n0 + threadIdx.x];
    __syncthreads();
    #pragma unroll
    for (int i = 0; i < 4; i++)
        out[(size_t)(n0 + threadIdx.y + i*8) * K + k0 + threadIdx.x] =
            __float2half(t[threadIdx.x][threadIdx.y + i*8]);
}

// interleave-transpose: out rows 2j = Wz[:,j], 2j+1 = Wh[:,j]  (per layer z)
__global__ void transpose_zh(const float* __restrict__ Wz,
                             const float* __restrict__ Wh,
                             __half* __restrict__ out)   // [L][1024][512]
{
    __shared__ float tz[32][33];
    __shared__ float th[32][33];
    int z = blockIdx.z;
    const float* wz = Wz + (size_t)z * DDIM * DDIM;
    const float* wh = Wh + (size_t)z * DDIM * DDIM;
    __half* o = out + (size_t)z * 2 * DDIM * DDIM;
    int j0 = blockIdx.x * 32, k0 = blockIdx.y * 32;
    #pragma unroll
    for (int i = 0; i < 4; i++) {
        int kk = threadIdx.y + i*8;
        tz[kk][threadIdx.x] = wz[(size_t)(k0 + kk) * DDIM + j0 + threadIdx.x];
        th[kk][threadIdx.x] = wh[(size_t)(k0 + kk) * DDIM + j0 + threadIdx.x];
    }
    __syncthreads();
    #pragma unroll
    for (int i = 0; i < 8; i++) {
        int nl = threadIdx.y + i*8;          // 0..63 local interleaved row
        int jl = nl >> 1;
        float val = (nl & 1) ? th[threadIdx.x][jl] : tz[threadIdx.x][jl];
        o[(size_t)(2*j0 + nl) * DDIM + k0 + threadIdx.x] = __float2half(val);
    }
}

// elementwise fp32 -> fp16 (pw_w is already [N][K])
__global__ void convert_h(const float* __restrict__ in, __half* __restrict__ out, int n)
{
    int i = blockIdx.x * blockDim.x + threadIdx.x;
    if (i < n) out[i] = __float2half(in[i]);
}

// ---------------- depthwise causal conv (K=4), fp16 out ----------------------
__global__ void dwconv_kernel(const float* __restrict__ x,
                              const float* __restrict__ w,
                              const float* __restrict__ wb,
                              __half* __restrict__ out)
{
    int idx = blockIdx.x * blockDim.x + threadIdx.x;
    if (idx >= MMR*DDIM) return;
    int c = idx % DDIM;
    int bs = idx / DDIM;
    int s = bs % SS;
    float acc = wb[c];
    #pragma unroll
    for (int k = 0; k < 4; k++) {
        int sp = s + k - 3;
        if (sp >= 0) acc += w[c*4 + k] * x[idx + (k-3)*DDIM];
    }
    out[idx] = __float2half(acc);
}

// ---------------- LayerNorm (512), warp-per-row; fp32 in -> fp16 out ---------
__global__ void ln_f2h(const float* __restrict__ in, __half* __restrict__ out,
                       const float* __restrict__ g, const float* __restrict__ b)
{
    int warp = threadIdx.x >> 5, lane = threadIdx.x & 31;
    int row = blockIdx.x * 8 + warp;
    const float* p = in + (size_t)row * DDIM;
    float vals[16];
    float s = 0.f;
    #pragma unroll
    for (int i = 0; i < 16; i++) { vals[i] = p[lane + i*32]; s += vals[i]; }
    #pragma unroll
    for (int o = 16; o > 0; o >>= 1) s += __shfl_xor_sync(0xffffffff, s, o);
    float mean = s * (1.f/DDIM);
    float vs = 0.f;
    #pragma unroll
    for (int i = 0; i < 16; i++) { float d = vals[i]-mean; vs += d*d; }
    #pragma unroll
    for (int o = 16; o > 0; o >>= 1) vs += __shfl_xor_sync(0xffffffff, vs, o);
    float inv = rsqrtf(vs * (1.f/DDIM) + 1e-5f);
    __half* q = out + (size_t)row * DDIM;
    #pragma unroll
    for (int i = 0; i < 16; i++) {
        int c = lane + i*32;
        q[c] = __float2half((vals[i]-mean) * inv * g[c] + b[c]);
    }
}

// LayerNorm fp16 in -> fp16 out (for mlp_in = LN(gru_in))
__global__ void ln_h2h(const __half* __restrict__ in, __half* __restrict__ out,
                       const float* __restrict__ g, const float* __restrict__ b)
{
    int warp = threadIdx.x >> 5, lane = threadIdx.x & 31;
    int row = blockIdx.x * 8 + warp;
    const __half* p = in + (size_t)row * DDIM;
    float vals[16];
    float s = 0.f;
    #pragma unroll
    for (int i = 0; i < 16; i++) { vals[i] = __half2float(p[lane + i*32]); s += vals[i]; }
    #pragma unroll
    for (int o = 16; o > 0; o >>= 1) s += __shfl_xor_sync(0xffffffff, s, o);
    float mean = s * (1.f/DDIM);
    float vs = 0.f;
    #pragma unroll
    for (int i = 0; i < 16; i++) { float d = vals[i]-mean; vs += d*d; }
    #pragma unroll
    for (int o = 16; o > 0; o >>= 1) vs += __shfl_xor_sync(0xffffffff, vs, o);
    float inv = rsqrtf(vs * (1.f/DDIM) + 1e-5f);
    __half* q = out + (size_t)row * DDIM;
    #pragma unroll
    for (int i = 0; i < 16; i++) {
        int c = lane + i*32;
        q[c] = __float2half((vals[i]-mean) * inv * g[c] + b[c]);
    }
}

// ---------------- scan pass1: read c,v (fp16) -> chunk carries P,V ----------
__global__ void scan_pass1(const __half* __restrict__ cb, const __half* __restrict__ vb,
                           float* __restrict__ Pb, float* __restrict__ Vb)
{
    int gid = blockIdx.x * blockDim.x + threadIdx.x;
    int b = gid / (DDIM*NCH);
    int r = gid - b*(DDIM*NCH);
    int chunk = r / DDIM;
    int d = r - chunk*DDIM;
    size_t base = ((size_t)b*SS + (size_t)chunk*CHK)*DDIM + d;
    float p = 1.f, v = 0.f;
    for (int i = 0; i < CHK; i++) {
        size_t o = base + (size_t)i*DDIM;
        float ci = __half2float(cb[o]);
        float vi = __half2float(vb[o]);
        v = fmaf(ci, v, vi);
        p *= ci;
    }
    int ch = (b*DDIM + d)*NCH + chunk;
    Pb[ch] = p; Vb[ch] = v;
}

__global__ void scan_pass2(const float* __restrict__ Pb, const float* __restrict__ Vb,
                           float* __restrict__ Hib)
{
    int ch = blockIdx.x * blockDim.x + threadIdx.x;
    if (ch >= BB*DDIM) return;
    float h = 0.5f;
    #pragma unroll
    for (int c = 0; c < NCH; c++) {
        Hib[ch*NCH + c] = h;
        h = fmaf(Pb[ch*NCH + c], h, Vb[ch*NCH + c]);
    }
}

__global__ void scan_pass3(const __half* __restrict__ cb, const __half* __restrict__ vb,
                           const float* __restrict__ Hib, float* __restrict__ xb)
{
    int gid = blockIdx.x * blockDim.x + threadIdx.x;
    int b = gid / (DDIM*NCH);
    int r = gid - b*(DDIM*NCH);
    int chunk = r / DDIM;
    int d = r - chunk*DDIM;
    size_t base = ((size_t)b*SS + (size_t)chunk*CHK)*DDIM + d;
    float h = Hib[(b*DDIM + d)*NCH + chunk];
    for (int i = 0; i < CHK; i++) {
        size_t o = base + (size_t)i*DDIM;
        h = fmaf(__half2float(cb[o]), h, __half2float(vb[o]));
        xb[o] += h;
    }
}

// -------------------------------- launch ------------------------------------
extern "C" void kernel_launch(void* const* d_in, const int* in_sizes, int n_in,
                              void* d_out, int out_size)
{
    const float* x     = (const float*)d_in[0];
    const float* dw_w  = (const float*)d_in[1];
    const float* dw_b  = (const float*)d_in[2];
    const float* pw_w  = (const float*)d_in[3];
    const float* pw_b  = (const float*)d_in[4];
    const float* ln1_g = (const float*)d_in[5];
    const float* ln1_b = (const float*)d_in[6];
    const float* Wz    = (const float*)d_in[7];
    const float* Wh    = (const float*)d_in[8];
    const float* lng   = (const float*)d_in[9];
    const float* lnb   = (const float*)d_in[10];
    const float* ln2_g = (const float*)d_in[11];
    const float* ln2_b = (const float*)d_in[12];
    const float* W1    = (const float*)d_in[13];
    const float* b1    = (const float*)d_in[14];
    const float* W2    = (const float*)d_in[15];
    const float* b2    = (const float*)d_in[16];
    float* out = (float*)d_out;

    float *xbuf, *Pb, *Vb, *Hib;
    __half *c16, *v16, *gin16, *cin16, *h16, *Wzh16, *W1T16, *W2T16, *pw16;
    cudaGetSymbolAddress((void**)&xbuf, g_xbuf);
    cudaGetSymbolAddress((void**)&Pb,   g_P);
    cudaGetSymbolAddress((void**)&Vb,   g_V);
    cudaGetSymbolAddress((void**)&Hib,  g_Hi);
    cudaGetSymbolAddress((void**)&c16,  g_c16);
    cudaGetSymbolAddress((void**)&v16,  g_v16);
    cudaGetSymbolAddress((void**)&gin16, g_gin16);
    cudaGetSymbolAddress((void**)&cin16, g_cin16);
    cudaGetSymbolAddress((void**)&h16,   g_h16);
    cudaGetSymbolAddress((void**)&Wzh16, g_Wzh16);
    cudaGetSymbolAddress((void**)&W1T16, g_W1T16);
    cudaGetSymbolAddress((void**)&W2T16, g_W2T16);
    cudaGetSymbolAddress((void**)&pw16,  g_pw16);

    cudaFuncSetAttribute(hgemm_kernel,
        cudaFuncAttributeMaxDynamicSharedMemorySize, SMEMSZ);

    const int NELT = MMR*DDIM;
    dim3 eltGrid((NELT + 255)/256);
    dim3 tb(32, 8);

    // 0) weight convert/transpose to fp16
    transpose_zh<<<dim3(DDIM/32, DDIM/32, LL), tb>>>(Wz, Wh, Wzh16);
    transpose_h<<<dim3(HH/32, DDIM/32, 1),   tb>>>(W1, W1T16, DDIM, HH);
    transpose_h<<<dim3(DDIM/32, HH/32, 1),   tb>>>(W2, W2T16, HH, DDIM);
    convert_h<<<(DDIM*DDIM + 255)/256, 256>>>(pw_w, pw16, DDIM*DDIM);

    // 1) depthwise conv -> cin16 (fp16)
    dwconv_kernel<<<eltGrid, 256>>>(x, dw_w, dw_b, cin16);

    // 2) pointwise conv + pw_b + residual x -> xbuf (fp32)
    hgemm_kernel<<<dim3(DDIM/128, MMR/128), NTHR, SMEMSZ>>>(
        cin16, pw16, xbuf, nullptr, nullptr, nullptr,
        MMR, DDIM, DDIM, pw_b, x, 0);

    // 3) gru_in = LN(xbuf, ln1) -> gin16
    ln_f2h<<<MMR/8, 256>>>(xbuf, gin16, ln1_g, ln1_b);

    // 4) GRU layers: ONE combined GEMM (N=1024, interleaved) w/ fused gating
    for (int l = 0; l < LL; l++) {
        hgemm_kernel<<<dim3(2*DDIM/128, MMR/128), NTHR, SMEMSZ>>>(
            gin16, Wzh16 + (size_t)l*2*DDIM*DDIM, nullptr, nullptr, c16, v16,
            MMR, 2*DDIM, DDIM, nullptr, nullptr, 0);
        scan_pass1<<<(BB*DDIM*NCH)/256, 256>>>(c16, v16, Pb, Vb);
        scan_pass2<<<(BB*DDIM + 255)/256, 256>>>(Pb, Vb, Hib);
        scan_pass3<<<(BB*DDIM*NCH)/256, 256>>>(c16, v16, Hib, xbuf);
        ln_f2h<<<MMR/8, 256>>>(xbuf, gin16, lng + l*DDIM, lnb + l*DDIM);
    }

    // 5) mlp_in = LN(gin16, ln2) -> cin16 (fp16)
    ln_h2h<<<MMR/8, 256>>>(gin16, cin16, ln2_g, ln2_b);

    // 6) hidden = relu(mlp_in @ W1 + b1) -> h16 (fp16)
    hgemm_kernel<<<dim3(HH/128, MMR/128), NTHR, SMEMSZ>>>(
        cin16, W1T16, nullptr, h16, nullptr, nullptr,
        MMR, HH, DDIM, b1, nullptr, 1);

    // 7) out = hidden @ W2 + b2 + xbuf
    hgemm_kernel<<<dim3(DDIM/128, MMR/128), NTHR, SMEMSZ>>>(
        h16, W2T16, out, nullptr, nullptr, nullptr,
        MMR, DDIM, HH, b2, xbuf, 0);
}

// round 16
// speedup vs baseline: 1.0970x; 1.0970x over previous
#include <cuda_runtime.h>
#include <cstdint>
#include <math.h>
#include <cuda_fp16.h>
#include <mma.h>
using namespace nvcuda;

// Fixed problem shapes
#define BB   4
#define SS   4096
#define DDIM 512
#define HH   2048
#define LL   3
#define MMR  (BB*SS)      // 16384 rows
#define CHK  128          // scan chunk length
#define NCH  (SS/CHK)     // 32 chunks per sequence

// GEMM tiling: 128x128 CTA tile, 8 warps (64x32), KTILE=64, 3-stage pipeline
#define KTILE 64
#define LDSA  72               // smem stride in halfs (64 + 8 pad)
#define ATILE (128*LDSA)       // 9216 halfs = 18432 B
#define STAGE (2*ATILE)        // A+B per stage (halfs)
#define NSTG  3
#define SMEMSZ (NSTG*STAGE*2)  // 110592 bytes (epilogue aliases stage 0)
#define NTHR  256
// epilogue smem (half offsets within smh): wbuf floats [0,4096), cs, vs
#define CSOFF 4096             // halfs
#define VSOFF (CSOFF + 128*68) // 12800
#define CSSTR 68

// ---------------- scratch (static device arrays; no allocation) --------------
__device__ float  g_xbuf[MMR*DDIM];   // residual stream (fp32)
__device__ float  g_P [BB*DDIM*NCH];
__device__ float  g_V [BB*DDIM*NCH];
__device__ float  g_Hi[BB*DDIM*NCH];
__device__ __half g_c16 [MMR*DDIM];   // gate c (fp16)
__device__ __half g_v16 [MMR*DDIM];   // gate v (fp16)
__device__ __half g_gin16[MMR*DDIM];  // LN outputs (GEMM A operand)
__device__ __half g_cin16[MMR*DDIM];  // dwconv out / mlp_in (GEMM A operand)
__device__ __half g_h16 [MMR*HH];     // MLP hidden (fp16)
// fp16 transposed weights [N][K]
__device__ __half g_Wzh16[LL*2*DDIM*DDIM];  // interleaved [1024][512] per layer
__device__ __half g_W1T16[HH*DDIM];
__device__ __half g_W2T16[DDIM*HH];
__device__ __half g_pw16 [DDIM*DDIM];

// ---------------- fp16 tensor-core GEMM, 128x128x64, 8 warps, 3-stage --------
// C[m,n] = sum_k A[m,k] * Bt[n,k]   (A fp16 [M,K], Bt fp16 [N,K], fp32 accum)
// gateC path: computes gates AND per-chunk scan carries (P,V) in-epilogue.
__device__ __forceinline__ void cpasync16(void* dst, const void* src)
{
    unsigned int d = (unsigned int)__cvta_generic_to_shared(dst);
    asm volatile("cp.async.cg.shared.global [%0], [%1], 16;\n" :: "r"(d), "l"(src));
}

__global__ void __launch_bounds__(NTHR, 2)
hgemm_kernel(const __half* __restrict__ A, const __half* __restrict__ Bt,
             float* __restrict__ C, __half* __restrict__ C16,
             __half* __restrict__ gateC, __half* __restrict__ gateV,
             float* __restrict__ Pb, float* __restrict__ Vb,
             int M, int N, int K,
             const float* __restrict__ bias, const float* __restrict__ resid,
             int dorelu)
{
    extern __shared__ __half smh[];
    float* epist = (float*)smh;       // aliases stage 0 (used post-mainloop)

    const int tid = threadIdx.x;
    const int wid = tid >> 5;
    const int lane = tid & 31;
    const int bm = blockIdx.y * 128;
    const int bn = blockIdx.x * 128;
    const int wm = (wid >> 2) * 64;   // warp grid 2(m) x 4(n)
    const int wn = (wid & 3) * 32;
    float* wbuf = epist + wid*256;    // per-warp 16x16 staging

    wmma::fragment<wmma::accumulator, 16, 16, 16, float> acc[4][2];
    #pragma unroll
    for (int i = 0; i < 4; i++)
        #pragma unroll
        for (int j = 0; j < 2; j++) wmma::fill_fragment(acc[i][j], 0.f);

    // ---- stage loaders: 128 rows x 64 halfs = 1024 16B-chunks -> 4/thread ---
    auto loadStage = [&](int stg, int k0) {
        __half* As = smh + stg*STAGE;
        __half* Bs = As + ATILE;
        #pragma unroll
        for (int i = 0; i < 4; i++) {
            int idx = tid + i*NTHR;
            int r = idx >> 3, c8 = (idx & 7) * 8;
            cpasync16(As + r*LDSA + c8, A + (size_t)(bm + r)*K + k0 + c8);
        }
        #pragma unroll
        for (int i = 0; i < 4; i++) {
            int idx = tid + i*NTHR;
            int r = idx >> 3, c8 = (idx & 7) * 8;
            cpasync16(Bs + r*LDSA + c8, Bt + (size_t)(bn + r)*K + k0 + c8);
        }
        asm volatile("cp.async.commit_group;\n");
    };

    const int nk = K / KTILE;
    loadStage(0, 0);
    if (nk > 1) loadStage(1, KTILE);

    for (int kt = 0; kt < nk; kt++) {
        if (kt + 1 < nk) {
            asm volatile("cp.async.wait_group 1;\n");
        } else {
            asm volatile("cp.async.wait_group 0;\n");
        }
        __syncthreads();
        if (kt + 2 < nk) loadStage((kt+2) % NSTG, (kt+2)*KTILE);

        const __half* a = smh + (kt % NSTG)*STAGE;
        const __half* b = a + ATILE;
        #pragma unroll
        for (int ks = 0; ks < 4; ks++) {
            const int kk = ks * 16;
            wmma::fragment<wmma::matrix_a, 16, 16, 16, half, wmma::row_major> af[4];
            #pragma unroll
            for (int i = 0; i < 4; i++)
                wmma::load_matrix_sync(af[i], a + (wm + i*16)*LDSA + kk, LDSA);
            wmma::fragment<wmma::matrix_b, 16, 16, 16, half, wmma::col_major> bf[2];
            #pragma unroll
            for (int j = 0; j < 2; j++)
                wmma::load_matrix_sync(bf[j], b + (wn + j*16)*LDSA + kk, LDSA);
            #pragma unroll
            for (int i = 0; i < 4; i++)
                #pragma unroll
                for (int j = 0; j < 2; j++)
                    wmma::mma_sync(acc[i][j], af[i], bf[j], acc[i][j]);
        }
    }
    __syncthreads();   // protect epilogue staging (aliases stage 0)

    // ---- epilogue: per-warp 16x16 staging ----
    #pragma unroll
    for (int i = 0; i < 4; i++) {
        #pragma unroll
        for (int j = 0; j < 2; j++) {
            wmma::store_matrix_sync(wbuf, acc[i][j], 16, wmma::mem_row_major);
            __syncwarp();
            int r = lane >> 1, c = (lane & 1) * 8;
            int row = bm + wm + i*16 + r;
            int col = bn + wn + j*16 + c;
            float4 v0 = *(float4*)&wbuf[r*16 + c];
            float4 v1 = *(float4*)&wbuf[r*16 + c + 4];
            if (gateC) {
                // interleaved cols: (k0,a0,k1,a1,...) -> 4 (k,a) pairs
                float kk_[4] = { v0.x, v0.z, v1.x, v1.z };
                float aa_[4] = { v0.y, v0.w, v1.y, v1.w };
                __half cw[4], vw[4];
                #pragma unroll
                for (int t = 0; t < 4; t++) {
                    float e  = __expf(kk_[t]);
                    float ci = 1.f / (1.f + e);      // sigmoid(-k)
                    float zi = e * ci;               // sigmoid(k)
                    float a  = aa_[t];
                    float gg = (a >= 0.f) ? (a + 0.5f)
                                          : (1.f / (1.f + __expf(-a)));
                    cw[t] = __float2half(ci);
                    vw[t] = __float2half(zi * gg);
                }
                int p = col >> 1;    // global pair index
                *(uint2*)&gateC[(size_t)row*DDIM + p] = *(uint2*)cw;
                *(uint2*)&gateV[(size_t)row*DDIM + p] = *(uint2*)vw;
                // stage into smem for in-epilogue chunk scan
                int rl = wm + i*16 + r;                 // 0..127 (timestep)
                int pl = (wn + j*16 + c) >> 1;          // 0..63 (pair, mult of 4)
                *(uint2*)&smh[CSOFF + rl*CSSTR + pl] = *(uint2*)cw;
                *(uint2*)&smh[VSOFF + rl*CSSTR + pl] = *(uint2*)vw;
            } else {
                if (bias) {
                    float4 b0 = *(const float4*)&bias[col];
                    float4 b1 = *(const float4*)&bias[col+4];
                    v0.x += b0.x; v0.y += b0.y; v0.z += b0.z; v0.w += b0.w;
                    v1.x += b1.x; v1.y += b1.y; v1.z += b1.z; v1.w += b1.w;
                }
                if (dorelu) {
                    v0.x = fmaxf(v0.x, 0.f); v0.y = fmaxf(v0.y, 0.f);
                    v0.z = fmaxf(v0.z, 0.f); v0.w = fmaxf(v0.w, 0.f);
                    v1.x = fmaxf(v1.x, 0.f); v1.y = fmaxf(v1.y, 0.f);
                    v1.z = fmaxf(v1.z, 0.f); v1.w = fmaxf(v1.w, 0.f);
                }
                if (resid) {
                    float4 r0 = *(const float4*)&resid[(size_t)row*N + col];
                    float4 r1 = *(const float4*)&resid[(size_t)row*N + col + 4];
                    v0.x += r0.x; v0.y += r0.y; v0.z += r0.z; v0.w += r0.w;
                    v1.x += r1.x; v1.y += r1.y; v1.z += r1.z; v1.w += r1.w;
                }
                if (C16) {
                    __half2 h[4];
                    h[0] = __floats2half2_rn(v0.x, v0.y);
                    h[1] = __floats2half2_rn(v0.z, v0.w);
                    h[2] = __floats2half2_rn(v1.x, v1.y);
                    h[3] = __floats2half2_rn(v1.z, v1.w);
                    *(uint4*)&C16[(size_t)row*N + col] = *(uint4*)h;
                } else {
                    *(float4*)&C[(size_t)row*N + col]     = v0;
                    *(float4*)&C[(size_t)row*N + col + 4] = v1;
                }
            }
            __syncwarp();
        }
    }

    // ---- in-epilogue chunk scan (replaces scan_pass1) ----
    if (gateC) {
        __syncthreads();
        if (tid < 64) {
            float p = 1.f, v = 0.f;
            #pragma unroll 8
            for (int i = 0; i < CHK; i++) {
                float ci = __half2float(smh[CSOFF + i*CSSTR + tid]);
                float vi = __half2float(smh[VSOFF + i*CSSTR + tid]);
                v = fmaf(ci, v, vi);
                p *= ci;
            }
            int b = bm >> 12;                 // bm / SS
            int chunk = (bm & (SS-1)) >> 7;   // (bm % SS) / CHK
            int d = (bn >> 1) + tid;
            int ch = (b*DDIM + d)*NCH + chunk;
            Pb[ch] = p; Vb[ch] = v;
        }
    }
}

// ---------------- weight transpose+convert: out16[n*K+k] = in[k*N+n] ---------
__global__ void transpose_h(const float* __restrict__ in, __half* __restrict__ out,
                            int K, int N)
{
    __shared__ float t[32][33];
    int z = blockIdx.z;
    in  += (size_t)z * K * N;
    out += (size_t)z * K * N;
    int n0 = blockIdx.x * 32, k0 = blockIdx.y * 32;
    #pragma unroll
    for (int i = 0; i < 4; i++)
        t[threadIdx.y + i*8][threadIdx.x] =
            in[(size_t)(k0 + threadIdx.y + i*8) * N + n0 + threadIdx.x];
    __syncthreads();
    #pragma unroll
    for (int i = 0; i < 4; i++)
        out[(size_t)(n0 + threadIdx.y + i*8) * K + k0 + threadIdx.x] =
            __float2half(t[threadIdx.x][threadIdx.y + i*8]);
}

// interleave-transpose: out rows 2j = Wz[:,j], 2j+1 = Wh[:,j]  (per layer z)
__global__ void transpose_zh(const float* __restrict__ Wz,
                             const float* __restrict__ Wh,
                             __half* __restrict__ out)   // [L][1024][512]
{
    __shared__ float tz[32][33];
    __shared__ float th[32][33];
    int z = blockIdx.z;
    const float* wz = Wz + (size_t)z * DDIM * DDIM;
    const float* wh = Wh + (size_t)z * DDIM * DDIM;
    __half* o = out + (size_t)z * 2 * DDIM * DDIM;
    int j0 = blockIdx.x * 32, k0 = blockIdx.y * 32;
    #pragma unroll
    for (int i = 0; i < 4; i++) {
        int kk = threadIdx.y + i*8;
        tz[kk][threadIdx.x] = wz[(size_t)(k0 + kk) * DDIM + j0 + threadIdx.x];
        th[kk][threadIdx.x] = wh[(size_t)(k0 + kk) * DDIM + j0 + threadIdx.x];
    }
    __syncthreads();
    #pragma unroll
    for (int i = 0; i < 8; i++) {
        int nl = threadIdx.y + i*8;          // 0..63 local interleaved row
        int jl = nl >> 1;
        float val = (nl & 1) ? th[threadIdx.x][jl] : tz[threadIdx.x][jl];
        o[(size_t)(2*j0 + nl) * DDIM + k0 + threadIdx.x] = __float2half(val);
    }
}

// elementwise fp32 -> fp16 (pw_w is already [N][K])
__global__ void convert_h(const float* __restrict__ in, __half* __restrict__ out, int n)
{
    int i = blockIdx.x * blockDim.x + threadIdx.x;
    if (i < n) out[i] = __float2half(in[i]);
}

// ---------------- depthwise causal conv (K=4), fp16 out ----------------------
__global__ void dwconv_kernel(const float* __restrict__ x,
                              const float* __restrict__ w,
                              const float* __restrict__ wb,
                              __half* __restrict__ out)
{
    int idx = blockIdx.x * blockDim.x + threadIdx.x;
    if (idx >= MMR*DDIM) return;
    int c = idx % DDIM;
    int bs = idx / DDIM;
    int s = bs % SS;
    float acc = wb[c];
    #pragma unroll
    for (int k = 0; k < 4; k++) {
        int sp = s + k - 3;
        if (sp >= 0) acc += w[c*4 + k] * x[idx + (k-3)*DDIM];
    }
    out[idx] = __float2half(acc);
}

// ---------------- LayerNorm (512), warp-per-row; fp32 in -> fp16 out ---------
__global__ void ln_f2h(const float* __restrict__ in, __half* __restrict__ out,
                       const float* __restrict__ g, const float* __restrict__ b)
{
    int warp = threadIdx.x >> 5, lane = threadIdx.x & 31;
    int row = blockIdx.x * 8 + warp;
    const float* p = in + (size_t)row * DDIM;
    float vals[16];
    float s = 0.f;
    #pragma unroll
    for (int i = 0; i < 16; i++) { vals[i] = p[lane + i*32]; s += vals[i]; }
    #pragma unroll
    for (int o = 16; o > 0; o >>= 1) s += __shfl_xor_sync(0xffffffff, s, o);
    float mean = s * (1.f/DDIM);
    float vs = 0.f;
    #pragma unroll
    for (int i = 0; i < 16; i++) { float d = vals[i]-mean; vs += d*d; }
    #pragma unroll
    for (int o = 16; o > 0; o >>= 1) vs += __shfl_xor_sync(0xffffffff, vs, o);
    float inv = rsqrtf(vs * (1.f/DDIM) + 1e-5f);
    __half* q = out + (size_t)row * DDIM;
    #pragma unroll
    for (int i = 0; i < 16; i++) {
        int c = lane + i*32;
        q[c] = __float2half((vals[i]-mean) * inv * g[c] + b[c]);
    }
}

// LayerNorm fp16 in -> fp16 out (for mlp_in = LN(gru_in))
__global__ void ln_h2h(const __half* __restrict__ in, __half* __restrict__ out,
                       const float* __restrict__ g, const float* __restrict__ b)
{
    int warp = threadIdx.x >> 5, lane = threadIdx.x & 31;
    int row = blockIdx.x * 8 + warp;
    const __half* p = in + (size_t)row * DDIM;
    float vals[16];
    float s = 0.f;
    #pragma unroll
    for (int i = 0; i < 16; i++) { vals[i] = __half2float(p[lane + i*32]); s += vals[i]; }
    #pragma unroll
    for (int o = 16; o > 0; o >>= 1) s += __shfl_xor_sync(0xffffffff, s, o);
    float mean = s * (1.f/DDIM);
    float vs = 0.f;
    #pragma unroll
    for (int i = 0; i < 16; i++) { float d = vals[i]-mean; vs += d*d; }
    #pragma unroll
    for (int o = 16; o > 0; o >>= 1) vs += __shfl_xor_sync(0xffffffff, vs, o);
    float inv = rsqrtf(vs * (1.f/DDIM) + 1e-5f);
    __half* q = out + (size_t)row * DDIM;
    #pragma unroll
    for (int i = 0; i < 16; i++) {
        int c = lane + i*32;
        q[c] = __float2half((vals[i]-mean) * inv * g[c] + b[c]);
    }
}

// ---------------- pass2: per-channel serial scan over 32 chunk carries -------
__global__ void scan_pass2(const float* __restrict__ Pb, const float* __restrict__ Vb,
                           float* __restrict__ Hib)
{
    int ch = blockIdx.x * blockDim.x + threadIdx.x;
    if (ch >= BB*DDIM) return;
    float h = 0.5f;
    #pragma unroll
    for (int c = 0; c < NCH; c++) {
        Hib[ch*NCH + c] = h;
        h = fmaf(Pb[ch*NCH + c], h, Vb[ch*NCH + c]);
    }
}

// ---------------- fused pass3 + LayerNorm: one CTA per (b,chunk) -------------
// 512 threads: phase1 thread=channel scans 128 steps, updates xbuf, stages x
// into smem (fp16). phase2: 16 warps x 8 rows do LN from smem -> gout.
__global__ void __launch_bounds__(512)
scan3_ln_kernel(const __half* __restrict__ cb, const __half* __restrict__ vb,
                const float* __restrict__ Hib, float* __restrict__ xb,
                __half* __restrict__ gout,
                const float* __restrict__ g, const float* __restrict__ beta)
{
    extern __shared__ __half xs[];   // [128][512] fp16, 128KB
    int bc = blockIdx.x;             // b*NCH + chunk
    int b = bc / NCH, chunk = bc - b*NCH;
    int d = threadIdx.x;
    size_t base = ((size_t)b*SS + (size_t)chunk*CHK)*DDIM + d;
    float h = Hib[(size_t)(b*DDIM + d)*NCH + chunk];
    for (int i = 0; i < CHK; i++) {
        size_t o = base + (size_t)i*DDIM;
        h = fmaf(__half2float(cb[o]), h, __half2float(vb[o]));
        float x = xb[o] + h;
        xb[o] = x;
        xs[i*DDIM + d] = __float2half(x);
    }
    __syncthreads();
    int wid = threadIdx.x >> 5, lane = threadIdx.x & 31;
    #pragma unroll
    for (int rr = 0; rr < 8; rr++) {
        int row = wid*8 + rr;
        const __half* p = xs + row*DDIM;
        float vals[16];
        float s = 0.f;
        #pragma unroll
        for (int i = 0; i < 16; i++) { vals[i] = __half2float(p[lane + i*32]); s += vals[i]; }
        #pragma unroll
        for (int o = 16; o > 0; o >>= 1) s += __shfl_xor_sync(0xffffffff, s, o);
        float mean = s * (1.f/DDIM);
        float vs = 0.f;
        #pragma unroll
        for (int i = 0; i < 16; i++) { float dd = vals[i]-mean; vs += dd*dd; }
        #pragma unroll
        for (int o = 16; o > 0; o >>= 1) vs += __shfl_xor_sync(0xffffffff, vs, o);
        float inv = rsqrtf(vs * (1.f/DDIM) + 1e-5f);
        __half* q = gout + ((size_t)(b*SS + chunk*CHK + row))*DDIM;
        #pragma unroll
        for (int i = 0; i < 16; i++) {
            int c = lane + i*32;
            q[c] = __float2half((vals[i]-mean) * inv * g[c] + beta[c]);
        }
    }
}

// -------------------------------- launch ------------------------------------
extern "C" void kernel_launch(void* const* d_in, const int* in_sizes, int n_in,
                              void* d_out, int out_size)
{
    const float* x     = (const float*)d_in[0];
    const float* dw_w  = (const float*)d_in[1];
    const float* dw_b  = (const float*)d_in[2];
    const float* pw_w  = (const float*)d_in[3];
    const float* pw_b  = (const float*)d_in[4];
    const float* ln1_g = (const float*)d_in[5];
    const float* ln1_b = (const float*)d_in[6];
    const float* Wz    = (const float*)d_in[7];
    const float* Wh    = (const float*)d_in[8];
    const float* lng   = (const float*)d_in[9];
    const float* lnb   = (const float*)d_in[10];
    const float* ln2_g = (const float*)d_in[11];
    const float* ln2_b = (const float*)d_in[12];
    const float* W1    = (const float*)d_in[13];
    const float* b1    = (const float*)d_in[14];
    const float* W2    = (const float*)d_in[15];
    const float* b2    = (const float*)d_in[16];
    float* out = (float*)d_out;

    float *xbuf, *Pb, *Vb, *Hib;
    __half *c16, *v16, *gin16, *cin16, *h16, *Wzh16, *W1T16, *W2T16, *pw16;
    cudaGetSymbolAddress((void**)&xbuf, g_xbuf);
    cudaGetSymbolAddress((void**)&Pb,   g_P);
    cudaGetSymbolAddress((void**)&Vb,   g_V);
    cudaGetSymbolAddress((void**)&Hib,  g_Hi);
    cudaGetSymbolAddress((void**)&c16,  g_c16);
    cudaGetSymbolAddress((void**)&v16,  g_v16);
    cudaGetSymbolAddress((void**)&gin16, g_gin16);
    cudaGetSymbolAddress((void**)&cin16, g_cin16);
    cudaGetSymbolAddress((void**)&h16,   g_h16);
    cudaGetSymbolAddress((void**)&Wzh16, g_Wzh16);
    cudaGetSymbolAddress((void**)&W1T16, g_W1T16);
    cudaGetSymbolAddress((void**)&W2T16, g_W2T16);
    cudaGetSymbolAddress((void**)&pw16,  g_pw16);

    cudaFuncSetAttribute(hgemm_kernel,
        cudaFuncAttributeMaxDynamicSharedMemorySize, SMEMSZ);
    cudaFuncSetAttribute(scan3_ln_kernel,
        cudaFuncAttributeMaxDynamicSharedMemorySize, CHK*DDIM*2);

    const int NELT = MMR*DDIM;
    dim3 eltGrid((NELT + 255)/256);
    dim3 tb(32, 8);

    // 0) weight convert/transpose to fp16
    transpose_zh<<<dim3(DDIM/32, DDIM/32, LL), tb>>>(Wz, Wh, Wzh16);
    transpose_h<<<dim3(HH/32, DDIM/32, 1),   tb>>>(W1, W1T16, DDIM, HH);
    transpose_h<<<dim3(DDIM/32, HH/32, 1),   tb>>>(W2, W2T16, HH, DDIM);
    convert_h<<<(DDIM*DDIM + 255)/256, 256>>>(pw_w, pw16, DDIM*DDIM);

    // 1) depthwise conv -> cin16 (fp16)
    dwconv_kernel<<<eltGrid, 256>>>(x, dw_w, dw_b, cin16);

    // 2) pointwise conv + pw_b + residual x -> xbuf (fp32)
    hgemm_kernel<<<dim3(DDIM/128, MMR/128), NTHR, SMEMSZ>>>(
        cin16, pw16, xbuf, nullptr, nullptr, nullptr, nullptr, nullptr,
        MMR, DDIM, DDIM, pw_b, x, 0);

    // 3) gru_in = LN(xbuf, ln1) -> gin16
    ln_f2h<<<MMR/8, 256>>>(xbuf, gin16, ln1_g, ln1_b);

    // 4) GRU layers: combined GEMM (N=1024) w/ fused gating + chunk scan;
    //    then tiny pass2; then fused pass3+LN.
    for (int l = 0; l < LL; l++) {
        hgemm_kernel<<<dim3(2*DDIM/128, MMR/128), NTHR, SMEMSZ>>>(
            gin16, Wzh16 + (size_t)l*2*DDIM*DDIM, nullptr, nullptr, c16, v16,
            Pb, Vb, MMR, 2*DDIM, DDIM, nullptr, nullptr, 0);
        scan_pass2<<<(BB*DDIM + 255)/256, 256>>>(Pb, Vb, Hib);
        scan3_ln_kernel<<<BB*NCH, 512, CHK*DDIM*2>>>(
            c16, v16, Hib, xbuf, gin16, lng + l*DDIM, lnb + l*DDIM);
    }

    // 5) mlp_in = LN(gin16, ln2) -> cin16 (fp16)
    ln_h2h<<<MMR/8, 256>>>(gin16, cin16, ln2_g, ln2_b);

    // 6) hidden = relu(mlp_in @ W1 + b1) -> h16 (fp16)
    hgemm_kernel<<<dim3(HH/128, MMR/128), NTHR, SMEMSZ>>>(
        cin16, W1T16, nullptr, h16, nullptr, nullptr, nullptr, nullptr,
        MMR, HH, DDIM, b1, nullptr, 1);

    // 7) out = hidden @ W2 + b2 + xbuf
    hgemm_kernel<<<dim3(DDIM/128, MMR/128), NTHR, SMEMSZ>>>(
        h16, W2T16, out, nullptr, nullptr, nullptr, nullptr, nullptr,
        MMR, DDIM, HH, b2, xbuf, 0);
}

// round 17
// speedup vs baseline: 1.1000x; 1.0027x over previous
#include <cuda_runtime.h>
#include <cstdint>
#include <math.h>
#include <cuda_fp16.h>

// Fixed problem shapes
#define BB   4
#define SS   4096
#define DDIM 512
#define HH   2048
#define LL   3
#define MMR  (BB*SS)      // 16384 rows
#define CHK  128          // scan chunk length
#define NCH  (SS/CHK)     // 32 chunks per sequence

// GEMM tiling: 128x128 CTA tile, 8 warps (64x32), KTILE=64, 3-stage pipeline
#define KTILE 64
#define LDSA  72               // smem stride in halfs (64 + 8 pad; 144B rows)
#define ATILE (128*LDSA)       // 9216 halfs = 18432 B
#define STAGE (2*ATILE)        // A+B per stage (halfs)
#define NSTG  3
#define SMEMSZ (NSTG*STAGE*2)  // 110592 bytes (epilogue gate-scan aliases stage 0)
#define NTHR  256
// gate-scan staging (half offsets in smh; aliases stage 0 post-mainloop)
#define CSSTR 68
#define CSOFF 0
#define VSOFF (128*CSSTR)      // 8704

// ---------------- scratch (static device arrays; no allocation) --------------
__device__ float  g_xbuf[MMR*DDIM];   // residual stream (fp32)
__device__ float  g_P [BB*DDIM*NCH];
__device__ float  g_V [BB*DDIM*NCH];
__device__ float  g_Hi[BB*DDIM*NCH];
__device__ __half g_c16 [MMR*DDIM];   // gate c (fp16)
__device__ __half g_v16 [MMR*DDIM];   // gate v (fp16)
__device__ __half g_gin16[MMR*DDIM];  // LN outputs (GEMM A operand)
__device__ __half g_cin16[MMR*DDIM];  // dwconv out / mlp_in (GEMM A operand)
__device__ __half g_h16 [MMR*HH];     // MLP hidden (fp16)
// fp16 transposed weights [N][K]
__device__ __half g_Wzh16[LL*2*DDIM*DDIM];  // interleaved [1024][512] per layer
__device__ __half g_W1T16[HH*DDIM];
__device__ __half g_W2T16[DDIM*HH];
__device__ __half g_pw16 [DDIM*DDIM];

// ---------------- PTX primitives ---------------------------------------------
__device__ __forceinline__ void cpasync16(void* dst, const void* src)
{
    unsigned int d = (unsigned int)__cvta_generic_to_shared(dst);
    asm volatile("cp.async.cg.shared.global [%0], [%1], 16;\n" :: "r"(d), "l"(src));
}
__device__ __forceinline__ void ldsm4(uint32_t* r, unsigned addr)
{
    asm volatile("ldmatrix.sync.aligned.m8n8.x4.shared.b16 {%0,%1,%2,%3}, [%4];"
                 : "=r"(r[0]), "=r"(r[1]), "=r"(r[2]), "=r"(r[3]) : "r"(addr));
}
__device__ __forceinline__ void mma16816(float* d, const uint32_t* a, const uint32_t* b)
{
    asm volatile("mma.sync.aligned.m16n8k16.row.col.f32.f16.f16.f32 "
                 "{%0,%1,%2,%3}, {%4,%5,%6,%7}, {%8,%9}, {%0,%1,%2,%3};"
                 : "+f"(d[0]), "+f"(d[1]), "+f"(d[2]), "+f"(d[3])
                 : "r"(a[0]), "r"(a[1]), "r"(a[2]), "r"(a[3]),
                   "r"(b[0]), "r"(b[1]));
}

// ---------------- fp16 tensor-core GEMM, mma.sync, 3-stage -------------------
// C[m,n] = sum_k A[m,k] * Bt[n,k]   (A fp16 [M,K], Bt fp16 [N,K], fp32 accum)
// gateC path: computes gates AND per-chunk scan carries (P,V) in-epilogue.
__global__ void __launch_bounds__(NTHR, 2)
hgemm_kernel(const __half* __restrict__ A, const __half* __restrict__ Bt,
             float* __restrict__ C, __half* __restrict__ C16,
             __half* __restrict__ gateC, __half* __restrict__ gateV,
             float* __restrict__ Pb, float* __restrict__ Vb,
             int M, int N, int K,
             const float* __restrict__ bias, const float* __restrict__ resid,
             int dorelu)
{
    extern __shared__ __half smh[];

    const int tid = threadIdx.x;
    const int wid = tid >> 5;
    const int lane = tid & 31;
    const int bm = blockIdx.y * 128;
    const int bn = blockIdx.x * 128;
    const int wm = (wid >> 2) * 64;   // warp grid 2(m) x 4(n)
    const int wn = (wid & 3) * 32;

    // ---- stage loaders: 128 rows x 64 halfs = 1024 16B-chunks -> 4/thread ---
    auto loadStage = [&](int stg, int k0) {
        __half* As = smh + stg*STAGE;
        __half* Bs = As + ATILE;
        #pragma unroll
        for (int i = 0; i < 4; i++) {
            int idx = tid + i*NTHR;
            int r = idx >> 3, c8 = (idx & 7) * 8;
            cpasync16(As + r*LDSA + c8, A + (size_t)(bm + r)*K + k0 + c8);
        }
        #pragma unroll
        for (int i = 0; i < 4; i++) {
            int idx = tid + i*NTHR;
            int r = idx >> 3, c8 = (idx & 7) * 8;
            cpasync16(Bs + r*LDSA + c8, Bt + (size_t)(bn + r)*K + k0 + c8);
        }
        asm volatile("cp.async.commit_group;\n");
    };

    // ldmatrix per-lane byte offsets (within a stage)
    unsigned sbase = (unsigned)__cvta_generic_to_shared(smh);
    unsigned aoff[4], boff[2];
    {
        int lr = (lane & 7) + ((lane >> 3) & 1) * 8;
        int lk = (lane >> 4) * 8;
        #pragma unroll
        for (int mt = 0; mt < 4; mt++)
            aoff[mt] = ((wm + mt*16 + lr)*LDSA + lk) * 2;
        int nr = (lane & 7) + (lane >> 4) * 8;
        int bk = ((lane >> 3) & 1) * 8;
        #pragma unroll
        for (int bt = 0; bt < 2; bt++)
            boff[bt] = ((wn + bt*16 + nr)*LDSA + bk) * 2 + ATILE*2;
    }

    float acc[4][4][4];
    #pragma unroll
    for (int i = 0; i < 4; i++)
        #pragma unroll
        for (int j = 0; j < 4; j++)
            #pragma unroll
            for (int e = 0; e < 4; e++) acc[i][j][e] = 0.f;

    const int nk = K / KTILE;
    loadStage(0, 0);
    if (nk > 1) loadStage(1, KTILE);

    for (int kt = 0; kt < nk; kt++) {
        if (kt + 1 < nk) {
            asm volatile("cp.async.wait_group 1;\n");
        } else {
            asm volatile("cp.async.wait_group 0;\n");
        }
        __syncthreads();
        if (kt + 2 < nk) loadStage((kt+2) % NSTG, (kt+2)*KTILE);

        unsigned stg = sbase + (unsigned)((kt % NSTG) * (STAGE*2));
        uint32_t ar[2][4][4], br[2][2][4];
        // preload ks=0
        #pragma unroll
        for (int mt = 0; mt < 4; mt++) ldsm4(ar[0][mt], stg + aoff[mt]);
        #pragma unroll
        for (int bt = 0; bt < 2; bt++) ldsm4(br[0][bt], stg + boff[bt]);

        #pragma unroll
        for (int ks = 0; ks < 4; ks++) {
            int cur = ks & 1;
            if (ks < 3) {
                int nxt = cur ^ 1;
                unsigned kb = (unsigned)((ks+1) * 16 * 2);
                #pragma unroll
                for (int mt = 0; mt < 4; mt++) ldsm4(ar[nxt][mt], stg + aoff[mt] + kb);
                #pragma unroll
                for (int bt = 0; bt < 2; bt++) ldsm4(br[nxt][bt], stg + boff[bt] + kb);
            }
            #pragma unroll
            for (int mt = 0; mt < 4; mt++)
                #pragma unroll
                for (int nt = 0; nt < 4; nt++)
                    mma16816(acc[mt][nt], ar[cur][mt],
                             &br[cur][nt >> 1][(nt & 1) * 2]);
        }
    }
    __syncthreads();   // all mainloop smem reads done before gate staging

    // ---- epilogue: register-direct (acc thread t holds cols 2(t%4), +1) -----
    const int qr = lane >> 2;        // 0..7
    const int qc = lane & 3;         // 0..3
    #pragma unroll
    for (int mt = 0; mt < 4; mt++) {
        int r0l = wm + mt*16 + qr;   // local row (and r0l+8)
        #pragma unroll
        for (int nt = 0; nt < 4; nt++) {
            float* d = acc[mt][nt];
            int colL = wn + nt*8 + 2*qc;
            if (gateC) {
                // (k,a) interleaved: d0=k(row0), d1=a(row0), d2=k(row0+8), d3=a
                int pl = colL >> 1;              // 0..63
                int p  = (bn >> 1) + pl;         // global pair index
                int row0 = bm + r0l;
                float e0  = __expf(d[0]);
                float c0  = 1.f / (1.f + e0);
                float z0  = e0 * c0;
                float a0  = d[1];
                float g0  = (a0 >= 0.f) ? (a0 + 0.5f) : (1.f / (1.f + __expf(-a0)));
                float e1  = __expf(d[2]);
                float c1  = 1.f / (1.f + e1);
                float z1  = e1 * c1;
                float a1  = d[3];
                float g1  = (a1 >= 0.f) ? (a1 + 0.5f) : (1.f / (1.f + __expf(-a1)));
                __half ch0 = __float2half(c0), vh0 = __float2half(z0*g0);
                __half ch1 = __float2half(c1), vh1 = __float2half(z1*g1);
                gateC[(size_t)row0*DDIM + p]     = ch0;
                gateV[(size_t)row0*DDIM + p]     = vh0;
                gateC[(size_t)(row0+8)*DDIM + p] = ch1;
                gateV[(size_t)(row0+8)*DDIM + p] = vh1;
                smh[CSOFF + r0l*CSSTR + pl]       = ch0;
                smh[VSOFF + r0l*CSSTR + pl]       = vh0;
                smh[CSOFF + (r0l+8)*CSSTR + pl]   = ch1;
                smh[VSOFF + (r0l+8)*CSSTR + pl]   = vh1;
            } else {
                int col = bn + colL;
                int row0 = bm + r0l, row1 = row0 + 8;
                float v0x = d[0], v0y = d[1], v1x = d[2], v1y = d[3];
                if (bias) {
                    float2 bb = *(const float2*)&bias[col];
                    v0x += bb.x; v0y += bb.y; v1x += bb.x; v1y += bb.y;
                }
                if (dorelu) {
                    v0x = fmaxf(v0x, 0.f); v0y = fmaxf(v0y, 0.f);
                    v1x = fmaxf(v1x, 0.f); v1y = fmaxf(v1y, 0.f);
                }
                if (resid) {
                    float2 r0 = *(const float2*)&resid[(size_t)row0*N + col];
                    float2 r1 = *(const float2*)&resid[(size_t)row1*N + col];
                    v0x += r0.x; v0y += r0.y; v1x += r1.x; v1y += r1.y;
                }
                if (C16) {
                    *(__half2*)&C16[(size_t)row0*N + col] = __floats2half2_rn(v0x, v0y);
                    *(__half2*)&C16[(size_t)row1*N + col] = __floats2half2_rn(v1x, v1y);
                } else {
                    float2 o0 = make_float2(v0x, v0y);
                    float2 o1 = make_float2(v1x, v1y);
                    *(float2*)&C[(size_t)row0*N + col] = o0;
                    *(float2*)&C[(size_t)row1*N + col] = o1;
                }
            }
        }
    }

    // ---- in-epilogue chunk scan (replaces scan_pass1) ----
    if (gateC) {
        __syncthreads();
        if (tid < 64) {
            float p = 1.f, v = 0.f;
            #pragma unroll 8
            for (int i = 0; i < CHK; i++) {
                float ci = __half2float(smh[CSOFF + i*CSSTR + tid]);
                float vi = __half2float(smh[VSOFF + i*CSSTR + tid]);
                v = fmaf(ci, v, vi);
                p *= ci;
            }
            int b = bm >> 12;                 // bm / SS
            int chunk = (bm & (SS-1)) >> 7;   // (bm % SS) / CHK
            int d = (bn >> 1) + tid;
            int ch = (b*DDIM + d)*NCH + chunk;
            Pb[ch] = p; Vb[ch] = v;
        }
    }
}

// ---------------- weight transpose+convert: out16[n*K+k] = in[k*N+n] ---------
__global__ void transpose_h(const float* __restrict__ in, __half* __restrict__ out,
                            int K, int N)
{
    __shared__ float t[32][33];
    int z = blockIdx.z;
    in  += (size_t)z * K * N;
    out += (size_t)z * K * N;
    int n0 = blockIdx.x * 32, k0 = blockIdx.y * 32;
    #pragma unroll
    for (int i = 0; i < 4; i++)
        t[threadIdx.y + i*8][threadIdx.x] =
            in[(size_t)(k0 + threadIdx.y + i*8) * N + n0 + threadIdx.x];
    __syncthreads();
    #pragma unroll
    for (int i = 0; i < 4; i++)
        out[(size_t)(n0 + threadIdx.y + i*8) * K + k0 + threadIdx.x] =
            __float2half(t[threadIdx.x][threadIdx.y + i*8]);
}

// interleave-transpose: out rows 2j = Wz[:,j], 2j+1 = Wh[:,j]  (per layer z)
__global__ void transpose_zh(const float* __restrict__ Wz,
                             const float* __restrict__ Wh,
                             __half* __restrict__ out)   // [L][1024][512]
{
    __shared__ float tz[32][33];
    __shared__ float th[32][33];
    int z = blockIdx.z;
    const float* wz = Wz + (size_t)z * DDIM * DDIM;
    const float* wh = Wh + (size_t)z * DDIM * DDIM;
    __half* o = out + (size_t)z * 2 * DDIM * DDIM;
    int j0 = blockIdx.x * 32, k0 = blockIdx.y * 32;
    #pragma unroll
    for (int i = 0; i < 4; i++) {
        int kk = threadIdx.y + i*8;
        tz[kk][threadIdx.x] = wz[(size_t)(k0 + kk) * DDIM + j0 + threadIdx.x];
        th[kk][threadIdx.x] = wh[(size_t)(k0 + kk) * DDIM + j0 + threadIdx.x];
    }
    __syncthreads();
    #pragma unroll
    for (int i = 0; i < 8; i++) {
        int nl = threadIdx.y + i*8;          // 0..63 local interleaved row
        int jl = nl >> 1;
        float val = (nl & 1) ? th[threadIdx.x][jl] : tz[threadIdx.x][jl];
        o[(size_t)(2*j0 + nl) * DDIM + k0 + threadIdx.x] = __float2half(val);
    }
}

// elementwise fp32 -> fp16 (pw_w is already [N][K])
__global__ void convert_h(const float* __restrict__ in, __half* __restrict__ out, int n)
{
    int i = blockIdx.x * blockDim.x + threadIdx.x;
    if (i < n) out[i] = __float2half(in[i]);
}

// ---------------- depthwise causal conv (K=4), fp16 out ----------------------
__global__ void dwconv_kernel(const float* __restrict__ x,
                              const float* __restrict__ w,
                              const float* __restrict__ wb,
                              __half* __restrict__ out)
{
    int idx = blockIdx.x * blockDim.x + threadIdx.x;
    if (idx >= MMR*DDIM) return;
    int c = idx % DDIM;
    int bs = idx / DDIM;
    int s = bs % SS;
    float acc = wb[c];
    #pragma unroll
    for (int k = 0; k < 4; k++) {
        int sp = s + k - 3;
        if (sp >= 0) acc += w[c*4 + k] * x[idx + (k-3)*DDIM];
    }
    out[idx] = __float2half(acc);
}

// ---------------- LayerNorm (512), warp-per-row; fp32 in -> fp16 out ---------
__global__ void ln_f2h(const float* __restrict__ in, __half* __restrict__ out,
                       const float* __restrict__ g, const float* __restrict__ b)
{
    int warp = threadIdx.x >> 5, lane = threadIdx.x & 31;
    int row = blockIdx.x * 8 + warp;
    const float* p = in + (size_t)row * DDIM;
    float vals[16];
    float s = 0.f;
    #pragma unroll
    for (int i = 0; i < 16; i++) { vals[i] = p[lane + i*32]; s += vals[i]; }
    #pragma unroll
    for (int o = 16; o > 0; o >>= 1) s += __shfl_xor_sync(0xffffffff, s, o);
    float mean = s * (1.f/DDIM);
    float vs = 0.f;
    #pragma unroll
    for (int i = 0; i < 16; i++) { float d = vals[i]-mean; vs += d*d; }
    #pragma unroll
    for (int o = 16; o > 0; o >>= 1) vs += __shfl_xor_sync(0xffffffff, vs, o);
    float inv = rsqrtf(vs * (1.f/DDIM) + 1e-5f);
    __half* q = out + (size_t)row * DDIM;
    #pragma unroll
    for (int i = 0; i < 16; i++) {
        int c = lane + i*32;
        q[c] = __float2half((vals[i]-mean) * inv * g[c] + b[c]);
    }
}

// LayerNorm fp16 in -> fp16 out (for mlp_in = LN(gru_in))
__global__ void ln_h2h(const __half* __restrict__ in, __half* __restrict__ out,
                       const float* __restrict__ g, const float* __restrict__ b)
{
    int warp = threadIdx.x >> 5, lane = threadIdx.x & 31;
    int row = blockIdx.x * 8 + warp;
    const __half* p = in + (size_t)row * DDIM;
    float vals[16];
    float s = 0.f;
    #pragma unroll
    for (int i = 0; i < 16; i++) { vals[i] = __half2float(p[lane + i*32]); s += vals[i]; }
    #pragma unroll
    for (int o = 16; o > 0; o >>= 1) s += __shfl_xor_sync(0xffffffff, s, o);
    float mean = s * (1.f/DDIM);
    float vs = 0.f;
    #pragma unroll
    for (int i = 0; i < 16; i++) { float d = vals[i]-mean; vs += d*d; }
    #pragma unroll
    for (int o = 16; o > 0; o >>= 1) vs += __shfl_xor_sync(0xffffffff, vs, o);
    float inv = rsqrtf(vs * (1.f/DDIM) + 1e-5f);
    __half* q = out + (size_t)row * DDIM;
    #pragma unroll
    for (int i = 0; i < 16; i++) {
        int c = lane + i*32;
        q[c] = __float2half((vals[i]-mean) * inv * g[c] + b[c]);
    }
}

// ---------------- pass2: per-channel serial scan over 32 chunk carries -------
__global__ void scan_pass2(const float* __restrict__ Pb, const float* __restrict__ Vb,
                           float* __restrict__ Hib)
{
    int ch = blockIdx.x * blockDim.x + threadIdx.x;
    if (ch >= BB*DDIM) return;
    float h = 0.5f;
    #pragma unroll
    for (int c = 0; c < NCH; c++) {
        Hib[ch*NCH + c] = h;
        h = fmaf(Pb[ch*NCH + c], h, Vb[ch*NCH + c]);
    }
}

// ---------------- fused pass3 + LayerNorm: one CTA per (b,chunk) -------------
__global__ void __launch_bounds__(512)
scan3_ln_kernel(const __half* __restrict__ cb, const __half* __restrict__ vb,
                const float* __restrict__ Hib, float* __restrict__ xb,
                __half* __restrict__ gout,
                const float* __restrict__ g, const float* __restrict__ beta)
{
    extern __shared__ __half xs[];   // [128][512] fp16, 128KB
    int bc = blockIdx.x;             // b*NCH + chunk
    int b = bc / NCH, chunk = bc - b*NCH;
    int d = threadIdx.x;
    size_t base = ((size_t)b*SS + (size_t)chunk*CHK)*DDIM + d;
    float h = Hib[(size_t)(b*DDIM + d)*NCH + chunk];
    for (int i = 0; i < CHK; i++) {
        size_t o = base + (size_t)i*DDIM;
        h = fmaf(__half2float(cb[o]), h, __half2float(vb[o]));
        float x = xb[o] + h;
        xb[o] = x;
        xs[i*DDIM + d] = __float2half(x);
    }
    __syncthreads();
    int wid = threadIdx.x >> 5, lane = threadIdx.x & 31;
    #pragma unroll
    for (int rr = 0; rr < 8; rr++) {
        int row = wid*8 + rr;
        const __half* p = xs + row*DDIM;
        float vals[16];
        float s = 0.f;
        #pragma unroll
        for (int i = 0; i < 16; i++) { vals[i] = __half2float(p[lane + i*32]); s += vals[i]; }
        #pragma unroll
        for (int o = 16; o > 0; o >>= 1) s += __shfl_xor_sync(0xffffffff, s, o);
        float mean = s * (1.f/DDIM);
        float vs = 0.f;
        #pragma unroll
        for (int i = 0; i < 16; i++) { float dd = vals[i]-mean; vs += dd*dd; }
        #pragma unroll
        for (int o = 16; o > 0; o >>= 1) vs += __shfl_xor_sync(0xffffffff, vs, o);
        float inv = rsqrtf(vs * (1.f/DDIM) + 1e-5f);
        __half* q = gout + ((size_t)(b*SS + chunk*CHK + row))*DDIM;
        #pragma unroll
        for (int i = 0; i < 16; i++) {
            int c = lane + i*32;
            q[c] = __float2half((vals[i]-mean) * inv * g[c] + beta[c]);
        }
    }
}

// -------------------------------- launch ------------------------------------
extern "C" void kernel_launch(void* const* d_in, const int* in_sizes, int n_in,
                              void* d_out, int out_size)
{
    const float* x     = (const float*)d_in[0];
    const float* dw_w  = (const float*)d_in[1];
    const float* dw_b  = (const float*)d_in[2];
    const float* pw_w  = (const float*)d_in[3];
    const float* pw_b  = (const float*)d_in[4];
    const float* ln1_g = (const float*)d_in[5];
    const float* ln1_b = (const float*)d_in[6];
    const float* Wz    = (const float*)d_in[7];
    const float* Wh    = (const float*)d_in[8];
    const float* lng   = (const float*)d_in[9];
    const float* lnb   = (const float*)d_in[10];
    const float* ln2_g = (const float*)d_in[11];
    const float* ln2_b = (const float*)d_in[12];
    const float* W1    = (const float*)d_in[13];
    const float* b1    = (const float*)d_in[14];
    const float* W2    = (const float*)d_in[15];
    const float* b2    = (const float*)d_in[16];
    float* out = (float*)d_out;

    float *xbuf, *Pb, *Vb, *Hib;
    __half *c16, *v16, *gin16, *cin16, *h16, *Wzh16, *W1T16, *W2T16, *pw16;
    cudaGetSymbolAddress((void**)&xbuf, g_xbuf);
    cudaGetSymbolAddress((void**)&Pb,   g_P);
    cudaGetSymbolAddress((void**)&Vb,   g_V);
    cudaGetSymbolAddress((void**)&Hib,  g_Hi);
    cudaGetSymbolAddress((void**)&c16,  g_c16);
    cudaGetSymbolAddress((void**)&v16,  g_v16);
    cudaGetSymbolAddress((void**)&gin16, g_gin16);
    cudaGetSymbolAddress((void**)&cin16, g_cin16);
    cudaGetSymbolAddress((void**)&h16,   g_h16);
    cudaGetSymbolAddress((void**)&Wzh16, g_Wzh16);
    cudaGetSymbolAddress((void**)&W1T16, g_W1T16);
    cudaGetSymbolAddress((void**)&W2T16, g_W2T16);
    cudaGetSymbolAddress((void**)&pw16,  g_pw16);

    cudaFuncSetAttribute(hgemm_kernel,
        cudaFuncAttributeMaxDynamicSharedMemorySize, SMEMSZ);
    cudaFuncSetAttribute(scan3_ln_kernel,
        cudaFuncAttributeMaxDynamicSharedMemorySize, CHK*DDIM*2);

    const int NELT = MMR*DDIM;
    dim3 eltGrid((NELT + 255)/256);
    dim3 tb(32, 8);

    // 0) weight convert/transpose to fp16
    transpose_zh<<<dim3(DDIM/32, DDIM/32, LL), tb>>>(Wz, Wh, Wzh16);
    transpose_h<<<dim3(HH/32, DDIM/32, 1),   tb>>>(W1, W1T16, DDIM, HH);
    transpose_h<<<dim3(DDIM/32, HH/32, 1),   tb>>>(W2, W2T16, HH, DDIM);
    convert_h<<<(DDIM*DDIM + 255)/256, 256>>>(pw_w, pw16, DDIM*DDIM);

    // 1) depthwise conv -> cin16 (fp16)
    dwconv_kernel<<<eltGrid, 256>>>(x, dw_w, dw_b, cin16);

    // 2) pointwise conv + pw_b + residual x -> xbuf (fp32)
    hgemm_kernel<<<dim3(DDIM/128, MMR/128), NTHR, SMEMSZ>>>(
        cin16, pw16, xbuf, nullptr, nullptr, nullptr, nullptr, nullptr,
        MMR, DDIM, DDIM, pw_b, x, 0);

    // 3) gru_in = LN(xbuf, ln1) -> gin16
    ln_f2h<<<MMR/8, 256>>>(xbuf, gin16, ln1_g, ln1_b);

    // 4) GRU layers: combined GEMM (N=1024) w/ fused gating + chunk scan;
    //    then tiny pass2; then fused pass3+LN.
    for (int l = 0; l < LL; l++) {
        hgemm_kernel<<<dim3(2*DDIM/128, MMR/128), NTHR, SMEMSZ>>>(
            gin16, Wzh16 + (size_t)l*2*DDIM*DDIM, nullptr, nullptr, c16, v16,
            Pb, Vb, MMR, 2*DDIM, DDIM, nullptr, nullptr, 0);
        scan_pass2<<<(BB*DDIM + 255)/256, 256>>>(Pb, Vb, Hib);
        scan3_ln_kernel<<<BB*NCH, 512, CHK*DDIM*2>>>(
            c16, v16, Hib, xbuf, gin16, lng + l*DDIM, lnb + l*DDIM);
    }

    // 5) mlp_in = LN(gin16, ln2) -> cin16 (fp16)
    ln_h2h<<<MMR/8, 256>>>(gin16, cin16, ln2_g, ln2_b);

    // 6) hidden = relu(mlp_in @ W1 + b1) -> h16 (fp16)
    hgemm_kernel<<<dim3(HH/128, MMR/128), NTHR, SMEMSZ>>>(
        cin16, W1T16, nullptr, h16, nullptr, nullptr, nullptr, nullptr,
        MMR, HH, DDIM, b1, nullptr, 1);

    // 7) out = hidden @ W2 + b2 + xbuf
    hgemm_kernel<<<dim3(DDIM/128, MMR/128), NTHR, SMEMSZ>>>(
        h16, W2T16, out, nullptr, nullptr, nullptr, nullptr, nullptr,
        MMR, DDIM, HH, b2, xbuf, 0);
}